// round 4
// baseline (speedup 1.0000x reference)
#include <cuda_runtime.h>

// 3D trilinear grid_sample, align_corners=False, padding_mode='border'
// image: [B, C, D, H, W] float32   (B=2, C=2, D=H=W=128)
// flow:  [B, 3, D, H, W] float32
// out:   [B, C, D, H, W] float32
//
// Two-pass:
//  (1) build duplicated channel-interleaved scratch:
//      g4[b][z][y][x] = (c0[x], c1[x], c0[x+1], c1[x+1])   (x+1 clamped)
//  (2) gather: each of the 4 corner rows = ONE aligned LDG.128 carrying
//      both channels at both x0 and x1.

#define B_ 2
#define C_ 2
#define D_ 128
#define H_ 128
#define W_ 128
#define N_ (D_ * H_ * W_)

__device__ float4 g_img4[B_][N_];

__global__ __launch_bounds__(256) void interleave_kernel(
    const float* __restrict__ image)
{
    // each thread handles 4 consecutive voxels (one row chunk) of one batch
    int t = blockIdx.x * blockDim.x + threadIdx.x;   // 0 .. B*N/4-1
    int b = t / (N_ / 4);
    int p4 = (t - b * (N_ / 4)) * 4;
    int x = p4 & (W_ - 1);                           // 0,4,...,124

    const float* img0 = image + ((size_t)b * C_ + 0) * N_;
    const float* img1 = image + ((size_t)b * C_ + 1) * N_;

    float4 c0 = __ldg(reinterpret_cast<const float4*>(img0 + p4));
    float4 c1 = __ldg(reinterpret_cast<const float4*>(img1 + p4));

    // element x+4 (clamped to row end)
    float c0n, c1n;
    if (x == W_ - 4) { c0n = c0.w; c1n = c1.w; }
    else             { c0n = __ldg(img0 + p4 + 4); c1n = __ldg(img1 + p4 + 4); }

    float4* dst = &g_img4[b][p4];
    dst[0] = make_float4(c0.x, c1.x, c0.y, c1.y);
    dst[1] = make_float4(c0.y, c1.y, c0.z, c1.z);
    dst[2] = make_float4(c0.z, c1.z, c0.w, c1.w);
    dst[3] = make_float4(c0.w, c1.w, c0n,  c1n);
}

__global__ __launch_bounds__(256) void warp3d_kernel(
    const float* __restrict__ flow,
    float* __restrict__ out)
{
    int tid = blockIdx.x * blockDim.x + threadIdx.x;
    if (tid >= B_ * N_) return;

    int b = tid / N_;
    int p = tid - b * N_;                       // z*H*W + y*W + x
    int x = p & (W_ - 1);
    int y = (p >> 7) & (H_ - 1);
    int z = p >> 14;

    const float* fb = flow + (size_t)b * 3 * N_;
    float fx = __ldg(fb + p);
    float fy = __ldg(fb + N_ + p);
    float fz = __ldg(fb + 2 * N_ + p);

    constexpr float sW = (float)W_ / (float)(W_ - 1);
    constexpr float sH = (float)H_ / (float)(H_ - 1);
    constexpr float sD = (float)D_ / (float)(D_ - 1);

    float ix = fminf(fmaxf(fmaf((float)x + fx, sW, -0.5f), 0.0f), (float)(W_ - 1));
    float iy = fminf(fmaxf(fmaf((float)y + fy, sH, -0.5f), 0.0f), (float)(H_ - 1));
    float iz = fminf(fmaxf(fmaf((float)z + fz, sD, -0.5f), 0.0f), (float)(D_ - 1));

    float x0f = floorf(ix), y0f = floorf(iy), z0f = floorf(iz);
    float tx = ix - x0f, ty = iy - y0f, tz = iz - z0f;

    int x0 = (int)x0f, y0 = (int)y0f, z0 = (int)z0f;
    int y1 = min(y0 + 1, H_ - 1);
    int z1 = min(z0 + 1, D_ - 1);

    const float4* img = g_img4[b];

    // 4 corner-row fetches; each carries (c0[x0],c1[x0],c0[x1],c1[x1])
    float4 q00 = __ldg(img + (z0 * H_ + y0) * W_ + x0);
    float4 q01 = __ldg(img + (z0 * H_ + y1) * W_ + x0);
    float4 q10 = __ldg(img + (z1 * H_ + y0) * W_ + x0);
    float4 q11 = __ldg(img + (z1 * H_ + y1) * W_ + x0);

    // lerp x (both channels), then y, then z
    float cx00x = fmaf(tx, q00.z - q00.x, q00.x);
    float cx00y = fmaf(tx, q00.w - q00.y, q00.y);
    float cx01x = fmaf(tx, q01.z - q01.x, q01.x);
    float cx01y = fmaf(tx, q01.w - q01.y, q01.y);
    float cx10x = fmaf(tx, q10.z - q10.x, q10.x);
    float cx10y = fmaf(tx, q10.w - q10.y, q10.y);
    float cx11x = fmaf(tx, q11.z - q11.x, q11.x);
    float cx11y = fmaf(tx, q11.w - q11.y, q11.y);

    float cy0x = fmaf(ty, cx01x - cx00x, cx00x);
    float cy0y = fmaf(ty, cx01y - cx00y, cx00y);
    float cy1x = fmaf(ty, cx11x - cx10x, cx10x);
    float cy1y = fmaf(ty, cx11y - cx10y, cx10y);

    out[((size_t)b * C_ + 0) * N_ + p] = fmaf(tz, cy1x - cy0x, cy0x);
    out[((size_t)b * C_ + 1) * N_ + p] = fmaf(tz, cy1y - cy0y, cy0y);
}

extern "C" void kernel_launch(void* const* d_in, const int* in_sizes, int n_in,
                              void* d_out, int out_size)
{
    const float* image = (const float*)d_in[0];
    const float* flow  = (const float*)d_in[1];
    float* out = (float*)d_out;

    {
        constexpr int total = B_ * N_ / 4;
        interleave_kernel<<<(total + 255) / 256, 256>>>(image);
    }
    {
        constexpr int total = B_ * N_;
        warp3d_kernel<<<(total + 255) / 256, 256>>>(flow, out);
    }
}

// round 5
// speedup vs baseline: 1.1040x; 1.1040x over previous
#include <cuda_runtime.h>

// 3D trilinear grid_sample, align_corners=False, padding_mode='border'
// image: [B, C, D, H, W] float32   (B=2, C=2, D=H=W=128)
// flow:  [B, 3, D, H, W] float32
// out:   [B, C, D, H, W] float32
//
// Pass 1: channel-interleave image into float2 scratch (33.5MB).
// Pass 2: each thread produces TWO x-consecutive output voxels:
//         vectorized flow loads (float2), 16 independent LDG.64 gathers
//         in flight, vectorized float2 stores.

#define B_ 2
#define C_ 2
#define D_ 128
#define H_ 128
#define W_ 128
#define N_ (D_ * H_ * W_)

__device__ float2 g_img2[B_][N_];

__global__ __launch_bounds__(256) void interleave_kernel(
    const float* __restrict__ image)
{
    int t = blockIdx.x * blockDim.x + threadIdx.x;   // 0 .. B*N/4-1
    int b = t / (N_ / 4);
    int p4 = (t - b * (N_ / 4)) * 4;

    const float4 c0 = __ldg(reinterpret_cast<const float4*>(
        image + ((size_t)b * C_ + 0) * N_ + p4));
    const float4 c1 = __ldg(reinterpret_cast<const float4*>(
        image + ((size_t)b * C_ + 1) * N_ + p4));

    float4* d4 = reinterpret_cast<float4*>(&g_img2[b][p4]);
    d4[0] = make_float4(c0.x, c1.x, c0.y, c1.y);
    d4[1] = make_float4(c0.z, c1.z, c0.w, c1.w);
}

// one output voxel's gather+lerp, given its coords and flow
struct Vox {
    int zy00, zy01, zy10, zy11, x0, x1;
    float tx, ty, tz;
};

__device__ __forceinline__ Vox setup(int x, int y, int z,
                                     float fx, float fy, float fz)
{
    constexpr float sW = (float)W_ / (float)(W_ - 1);
    constexpr float sH = (float)H_ / (float)(H_ - 1);
    constexpr float sD = (float)D_ / (float)(D_ - 1);

    float ix = fminf(fmaxf(fmaf((float)x + fx, sW, -0.5f), 0.0f), (float)(W_ - 1));
    float iy = fminf(fmaxf(fmaf((float)y + fy, sH, -0.5f), 0.0f), (float)(H_ - 1));
    float iz = fminf(fmaxf(fmaf((float)z + fz, sD, -0.5f), 0.0f), (float)(D_ - 1));

    float x0f = floorf(ix), y0f = floorf(iy), z0f = floorf(iz);

    Vox v;
    v.tx = ix - x0f; v.ty = iy - y0f; v.tz = iz - z0f;
    int x0 = (int)x0f, y0 = (int)y0f, z0 = (int)z0f;
    v.x0 = x0;
    v.x1 = min(x0 + 1, W_ - 1);
    int y1 = min(y0 + 1, H_ - 1);
    int z1 = min(z0 + 1, D_ - 1);
    v.zy00 = (z0 * H_ + y0) * W_;
    v.zy01 = (z0 * H_ + y1) * W_;
    v.zy10 = (z1 * H_ + y0) * W_;
    v.zy11 = (z1 * H_ + y1) * W_;
    return v;
}

__global__ __launch_bounds__(256) void warp3d_kernel(
    const float* __restrict__ flow,
    float* __restrict__ out)
{
    int tid = blockIdx.x * blockDim.x + threadIdx.x;   // 0 .. B*N/2-1
    int b = tid / (N_ / 2);
    int p = (tid - b * (N_ / 2)) * 2;           // even voxel index

    int x = p & (W_ - 1);
    int y = (p >> 7) & (H_ - 1);
    int z = p >> 14;

    const float* fb = flow + (size_t)b * 3 * N_;
    float2 fx2 = __ldg(reinterpret_cast<const float2*>(fb + p));
    float2 fy2 = __ldg(reinterpret_cast<const float2*>(fb + N_ + p));
    float2 fz2 = __ldg(reinterpret_cast<const float2*>(fb + 2 * N_ + p));

    Vox va = setup(x,     y, z, fx2.x, fy2.x, fz2.x);
    Vox vb = setup(x + 1, y, z, fx2.y, fy2.y, fz2.y);

    const float2* img = g_img2[b];

    // issue all 16 gathers before any math
    float2 a000 = __ldg(img + va.zy00 + va.x0);
    float2 a001 = __ldg(img + va.zy00 + va.x1);
    float2 a010 = __ldg(img + va.zy01 + va.x0);
    float2 a011 = __ldg(img + va.zy01 + va.x1);
    float2 a100 = __ldg(img + va.zy10 + va.x0);
    float2 a101 = __ldg(img + va.zy10 + va.x1);
    float2 a110 = __ldg(img + va.zy11 + va.x0);
    float2 a111 = __ldg(img + va.zy11 + va.x1);

    float2 b000 = __ldg(img + vb.zy00 + vb.x0);
    float2 b001 = __ldg(img + vb.zy00 + vb.x1);
    float2 b010 = __ldg(img + vb.zy01 + vb.x0);
    float2 b011 = __ldg(img + vb.zy01 + vb.x1);
    float2 b100 = __ldg(img + vb.zy10 + vb.x0);
    float2 b101 = __ldg(img + vb.zy10 + vb.x1);
    float2 b110 = __ldg(img + vb.zy11 + vb.x0);
    float2 b111 = __ldg(img + vb.zy11 + vb.x1);

    // trilinear for voxel A (both channels)
    float acx00x = fmaf(va.tx, a001.x - a000.x, a000.x);
    float acx00y = fmaf(va.tx, a001.y - a000.y, a000.y);
    float acx01x = fmaf(va.tx, a011.x - a010.x, a010.x);
    float acx01y = fmaf(va.tx, a011.y - a010.y, a010.y);
    float acx10x = fmaf(va.tx, a101.x - a100.x, a100.x);
    float acx10y = fmaf(va.tx, a101.y - a100.y, a100.y);
    float acx11x = fmaf(va.tx, a111.x - a110.x, a110.x);
    float acx11y = fmaf(va.tx, a111.y - a110.y, a110.y);
    float acy0x = fmaf(va.ty, acx01x - acx00x, acx00x);
    float acy0y = fmaf(va.ty, acx01y - acx00y, acx00y);
    float acy1x = fmaf(va.ty, acx11x - acx10x, acx10x);
    float acy1y = fmaf(va.ty, acx11y - acx10y, acx10y);
    float aoutx = fmaf(va.tz, acy1x - acy0x, acy0x);
    float aouty = fmaf(va.tz, acy1y - acy0y, acy0y);

    // trilinear for voxel B (both channels)
    float bcx00x = fmaf(vb.tx, b001.x - b000.x, b000.x);
    float bcx00y = fmaf(vb.tx, b001.y - b000.y, b000.y);
    float bcx01x = fmaf(vb.tx, b011.x - b010.x, b010.x);
    float bcx01y = fmaf(vb.tx, b011.y - b010.y, b010.y);
    float bcx10x = fmaf(vb.tx, b101.x - b100.x, b100.x);
    float bcx10y = fmaf(vb.tx, b101.y - b100.y, b100.y);
    float bcx11x = fmaf(vb.tx, b111.x - b110.x, b110.x);
    float bcx11y = fmaf(vb.tx, b111.y - b110.y, b110.y);
    float bcy0x = fmaf(vb.ty, bcx01x - bcx00x, bcx00x);
    float bcy0y = fmaf(vb.ty, bcx01y - bcx00y, bcx00y);
    float bcy1x = fmaf(vb.ty, bcx11x - bcx10x, bcx10x);
    float bcy1y = fmaf(vb.ty, bcx11y - bcx10y, bcx10y);
    float boutx = fmaf(vb.tz, bcy1x - bcy0x, bcy0x);
    float bouty = fmaf(vb.tz, bcy1y - bcy0y, bcy0y);

    float* o0 = out + ((size_t)b * C_ + 0) * N_ + p;
    float* o1 = out + ((size_t)b * C_ + 1) * N_ + p;
    *reinterpret_cast<float2*>(o0) = make_float2(aoutx, boutx);
    *reinterpret_cast<float2*>(o1) = make_float2(aouty, bouty);
}

extern "C" void kernel_launch(void* const* d_in, const int* in_sizes, int n_in,
                              void* d_out, int out_size)
{
    const float* image = (const float*)d_in[0];
    const float* flow  = (const float*)d_in[1];
    float* out = (float*)d_out;

    {
        constexpr int total = B_ * N_ / 4;
        interleave_kernel<<<total / 256, 256>>>(image);
    }
    {
        constexpr int total = B_ * N_ / 2;
        warp3d_kernel<<<total / 256, 256>>>(flow, out);
    }
}

// round 6
// speedup vs baseline: 1.2581x; 1.1396x over previous
#include <cuda_runtime.h>
#include <cuda_fp16.h>

// 3D trilinear grid_sample, align_corners=False, padding_mode='border'
// image: [B, C, D, H, W] float32   (B=2, C=2, D=H=W=128)
// flow:  [B, 3, D, H, W] float32
// out:   [B, C, D, H, W] float32
//
// Pass 1: repack image into fp16 scratch, 8B/voxel:
//         pair.lo = half2(c0[x],   c1[x])
//         pair.hi = half2(c0[x+1], c1[x+1])   (x+1 clamped at row end)
// Pass 2: gather — each of the 4 corner rows is ONE LDG.64 that carries
//         both channels at both x0 and x1. Interpolate in fp32.

#define B_ 2
#define C_ 2
#define D_ 128
#define H_ 128
#define W_ 128
#define N_ (D_ * H_ * W_)

struct __align__(8) Pair { __half2 lo, hi; };

__device__ Pair g_imgh[B_][N_];

__global__ __launch_bounds__(256) void interleave_kernel(
    const float* __restrict__ image)
{
    // each thread handles 4 consecutive voxels of one row of one batch
    int t = blockIdx.x * blockDim.x + threadIdx.x;   // 0 .. B*N/4-1
    int b = t / (N_ / 4);
    int p4 = (t - b * (N_ / 4)) * 4;
    int x = p4 & (W_ - 1);                           // 0,4,...,124

    const float* img0 = image + ((size_t)b * C_ + 0) * N_;
    const float* img1 = image + ((size_t)b * C_ + 1) * N_;

    float4 c0 = __ldg(reinterpret_cast<const float4*>(img0 + p4));
    float4 c1 = __ldg(reinterpret_cast<const float4*>(img1 + p4));

    float c0n, c1n;                                  // element x+4, clamped
    if (x == W_ - 4) { c0n = c0.w; c1n = c1.w; }
    else             { c0n = __ldg(img0 + p4 + 4); c1n = __ldg(img1 + p4 + 4); }

    Pair pr[4];
    pr[0].lo = __floats2half2_rn(c0.x, c1.x);
    pr[0].hi = __floats2half2_rn(c0.y, c1.y);
    pr[1].lo = __floats2half2_rn(c0.y, c1.y);
    pr[1].hi = __floats2half2_rn(c0.z, c1.z);
    pr[2].lo = __floats2half2_rn(c0.z, c1.z);
    pr[2].hi = __floats2half2_rn(c0.w, c1.w);
    pr[3].lo = __floats2half2_rn(c0.w, c1.w);
    pr[3].hi = __floats2half2_rn(c0n,  c1n);

    // 32B contiguous store
    uint4* dst = reinterpret_cast<uint4*>(&g_imgh[b][p4]);
    const uint4* src = reinterpret_cast<const uint4*>(pr);
    dst[0] = src[0];
    dst[1] = src[1];
}

__device__ __forceinline__ void fetch2(const Pair* __restrict__ img, int idx,
                                       float2& v0, float2& v1)
{
    uint2 q = __ldg(reinterpret_cast<const uint2*>(img + idx));
    v0 = __half22float2(*reinterpret_cast<const __half2*>(&q.x));
    v1 = __half22float2(*reinterpret_cast<const __half2*>(&q.y));
}

__global__ __launch_bounds__(256) void warp3d_kernel(
    const float* __restrict__ flow,
    float* __restrict__ out)
{
    int tid = blockIdx.x * blockDim.x + threadIdx.x;
    int b = tid >> 21;                           // tid / N_
    int p = tid & (N_ - 1);                      // z*H*W + y*W + x

    int x = p & (W_ - 1);
    int y = (p >> 7) & (H_ - 1);
    int z = p >> 14;

    const float* fb = flow + (size_t)b * 3 * N_;
    float fx = __ldg(fb + p);
    float fy = __ldg(fb + N_ + p);
    float fz = __ldg(fb + 2 * N_ + p);

    constexpr float sW = (float)W_ / (float)(W_ - 1);
    constexpr float sH = (float)H_ / (float)(H_ - 1);
    constexpr float sD = (float)D_ / (float)(D_ - 1);

    float ix = fminf(fmaxf(fmaf((float)x + fx, sW, -0.5f), 0.0f), (float)(W_ - 1));
    float iy = fminf(fmaxf(fmaf((float)y + fy, sH, -0.5f), 0.0f), (float)(H_ - 1));
    float iz = fminf(fmaxf(fmaf((float)z + fz, sD, -0.5f), 0.0f), (float)(D_ - 1));

    float x0f = floorf(ix), y0f = floorf(iy), z0f = floorf(iz);
    float tx = ix - x0f, ty = iy - y0f, tz = iz - z0f;

    int x0 = (int)x0f, y0 = (int)y0f, z0 = (int)z0f;
    int y1 = min(y0 + 1, H_ - 1);
    int z1 = min(z0 + 1, D_ - 1);

    const Pair* img = g_imgh[b];

    float2 v000, v001, v010, v011, v100, v101, v110, v111;
    fetch2(img, (z0 * H_ + y0) * W_ + x0, v000, v001);
    fetch2(img, (z0 * H_ + y1) * W_ + x0, v010, v011);
    fetch2(img, (z1 * H_ + y0) * W_ + x0, v100, v101);
    fetch2(img, (z1 * H_ + y1) * W_ + x0, v110, v111);

    // lerp x (both channels), then y, then z — in fp32
    float cx00x = fmaf(tx, v001.x - v000.x, v000.x);
    float cx00y = fmaf(tx, v001.y - v000.y, v000.y);
    float cx01x = fmaf(tx, v011.x - v010.x, v010.x);
    float cx01y = fmaf(tx, v011.y - v010.y, v010.y);
    float cx10x = fmaf(tx, v101.x - v100.x, v100.x);
    float cx10y = fmaf(tx, v101.y - v100.y, v100.y);
    float cx11x = fmaf(tx, v111.x - v110.x, v110.x);
    float cx11y = fmaf(tx, v111.y - v110.y, v110.y);

    float cy0x = fmaf(ty, cx01x - cx00x, cx00x);
    float cy0y = fmaf(ty, cx01y - cx00y, cx00y);
    float cy1x = fmaf(ty, cx11x - cx10x, cx10x);
    float cy1y = fmaf(ty, cx11y - cx10y, cx10y);

    out[((size_t)b * C_ + 0) * N_ + p] = fmaf(tz, cy1x - cy0x, cy0x);
    out[((size_t)b * C_ + 1) * N_ + p] = fmaf(tz, cy1y - cy0y, cy0y);
}

extern "C" void kernel_launch(void* const* d_in, const int* in_sizes, int n_in,
                              void* d_out, int out_size)
{
    const float* image = (const float*)d_in[0];
    const float* flow  = (const float*)d_in[1];
    float* out = (float*)d_out;

    {
        constexpr int total = B_ * N_ / 4;
        interleave_kernel<<<total / 256, 256>>>(image);
    }
    {
        constexpr int total = B_ * N_;
        warp3d_kernel<<<total / 256, 256>>>(flow, out);
    }
}